// round 16
// baseline (speedup 1.0000x reference)
#include <cuda_runtime.h>
#include <math.h>

#define T_STEPS 8192
#define M_DIM   1024
#define N_DIM   2048

#define GBLOCKS        128
#define ROWS_PER_BLOCK 16    // N_DIM / GBLOCKS
#define RNN_THREADS    256
#define ARR_PER_STEP   1024u // 8 warps x 128 blocks arrivals per step

// Scratch for the batched input projection (allocation-free rule: device global).
__device__ float g_pre[(size_t)T_STEPS * N_DIM];

// ONE monotone arrival counter; per-WARP arrivals (8 per block per step).
// Per launch: 1024 * 8192 adds == 0 mod 1024 and the counter starts at 0, so
// at every launch boundary it is a multiple of 1024. Before any block reads
// its base, at most 8*127 = 1016 < 1024 foreign step-0 arrivals can exist
// (a block reads base before its own arrivals; step-1 arrivals require ALL
// 1024 step-0 arrivals, hence all base reads). So flooring the first read to
// a multiple of 1024 gives a consistent epoch base in every block. Signed
// compares handle wrap; monotone, no resets -> replay-safe, deadlock-free.
__device__ unsigned g_ctr;

// ---------------------------------------------------------------------------
// Inline PTX helpers
// ---------------------------------------------------------------------------
__device__ __forceinline__ unsigned ld_acq(const unsigned* p) {
    unsigned v;
    asm volatile("ld.acquire.gpu.u32 %0, [%1];" : "=r"(v) : "l"(p) : "memory");
    return v;
}
__device__ __forceinline__ void red_rel_add1(unsigned* p) {
    asm volatile("red.release.gpu.global.add.u32 [%0], %1;"
                 :: "l"(p), "r"(1u) : "memory");
}
__device__ __forceinline__ void fma2(unsigned long long& d,
                                     unsigned long long a,
                                     unsigned long long b) {
    asm("fma.rn.f32x2 %0, %1, %2, %3;" : "=l"(d) : "l"(a), "l"(b), "l"(d));
}
__device__ __forceinline__ unsigned long long add2(unsigned long long a,
                                                   unsigned long long b) {
    unsigned long long d;
    asm("add.rn.f32x2 %0, %1, %2;" : "=l"(d) : "l"(a), "l"(b));
    return d;
}
__device__ __forceinline__ float hsum2(unsigned long long v) {
    float lo, hi;
    asm("mov.b64 {%0, %1}, %2;" : "=f"(lo), "=f"(hi) : "l"(v));
    return lo + hi;
}

// ---------------------------------------------------------------------------
// Kernel 1: pre = X @ W_ih^T + (b_ih + b_hh)   (unchanged, proven)
// ---------------------------------------------------------------------------
__global__ __launch_bounds__(256) void gemm_pre_kernel(
    const float* __restrict__ X,
    const float* __restrict__ Wih,
    const float* __restrict__ b_ih,
    const float* __restrict__ b_hh)
{
    __shared__ float As[8][128];
    __shared__ float Bs[8][128];

    const int tid = threadIdx.x;
    const int rowBase = blockIdx.x * 128;
    const int colBase = blockIdx.y * 128;
    const int tx = tid & 15;
    const int ty = tid >> 4;

    float acc[8][8];
#pragma unroll
    for (int i = 0; i < 8; i++)
#pragma unroll
        for (int j = 0; j < 8; j++) acc[i][j] = 0.0f;

    const int lr = tid >> 1;
    const int lq = (tid & 1) * 4;

    for (int k0 = 0; k0 < M_DIM; k0 += 8) {
        float4 av = *(const float4*)&X  [(size_t)(rowBase + lr) * M_DIM + k0 + lq];
        float4 bv = *(const float4*)&Wih[(size_t)(colBase + lr) * M_DIM + k0 + lq];

        __syncthreads();
        As[lq + 0][lr] = av.x;
        As[lq + 1][lr] = av.y;
        As[lq + 2][lr] = av.z;
        As[lq + 3][lr] = av.w;
        Bs[lq + 0][lr] = bv.x;
        Bs[lq + 1][lr] = bv.y;
        Bs[lq + 2][lr] = bv.z;
        Bs[lq + 3][lr] = bv.w;
        __syncthreads();

#pragma unroll
        for (int k = 0; k < 8; k++) {
            float4 a0 = ((const float4*)As[k])[ty];
            float4 a1 = ((const float4*)As[k])[ty + 16];
            float4 b0 = ((const float4*)Bs[k])[tx];
            float4 b1 = ((const float4*)Bs[k])[tx + 16];
            float a[8] = {a0.x, a0.y, a0.z, a0.w, a1.x, a1.y, a1.z, a1.w};
            float b[8] = {b0.x, b0.y, b0.z, b0.w, b1.x, b1.y, b1.z, b1.w};
#pragma unroll
            for (int i = 0; i < 8; i++)
#pragma unroll
                for (int j = 0; j < 8; j++)
                    acc[i][j] = fmaf(a[i], b[j], acc[i][j]);
        }
    }

    const int n0 = colBase + tx * 4;
    const int n1 = colBase + 64 + tx * 4;
    float bias[8];
#pragma unroll
    for (int j = 0; j < 4; j++) {
        bias[j]     = b_ih[n0 + j] + b_hh[n0 + j];
        bias[j + 4] = b_ih[n1 + j] + b_hh[n1 + j];
    }

#pragma unroll
    for (int i = 0; i < 8; i++) {
        int m = rowBase + ((i < 4) ? (ty * 4 + i) : (64 + ty * 4 + (i - 4)));
        float4 o0, o1;
        o0.x = acc[i][0] + bias[0];
        o0.y = acc[i][1] + bias[1];
        o0.z = acc[i][2] + bias[2];
        o0.w = acc[i][3] + bias[3];
        o1.x = acc[i][4] + bias[4];
        o1.y = acc[i][5] + bias[5];
        o1.z = acc[i][6] + bias[6];
        o1.w = acc[i][7] + bias[7];
        *(float4*)&g_pre[(size_t)m * N_DIM + n0] = o0;
        *(float4*)&g_pre[(size_t)m * N_DIM + n1] = o1;
    }
}

// ---------------------------------------------------------------------------
// Kernel 2: persistent RNN recurrence (R12 WIN + two refinements):
//   arrivals: per-WARP red.release.add right after each warp's Y store
//             (bottom __syncthreads removed; stragglers decoupled)
//   detect:   ONE thread/block, acquire-poll with __nanosleep(64)
// ---------------------------------------------------------------------------
__global__ __launch_bounds__(RNN_THREADS, 1) void rnn_kernel(
    const float* __restrict__ Whh,
    float* __restrict__ Y)
{
    const int tid  = threadIdx.x;
    const int b    = blockIdx.x;
    const int warp = tid >> 5;
    const int lane = tid & 31;
    const int row0 = b * ROWS_PER_BLOCK + 2 * warp;

    // Warp's two W_hh rows in registers, pre-packed as f32x2 pairs.
    unsigned long long wA[32], wB[32];
    {
        const ulonglong2* WA = (const ulonglong2*)(Whh + (size_t)row0 * N_DIM);
        const ulonglong2* WB = (const ulonglong2*)(Whh + (size_t)(row0 + 1) * N_DIM);
#pragma unroll
        for (int i = 0; i < 16; i++) {
            ulonglong2 va = WA[i * 32 + lane];
            ulonglong2 vb = WB[i * 32 + lane];
            wA[2 * i]     = va.x;
            wA[2 * i + 1] = va.y;
            wB[2 * i]     = vb.x;
            wB[2 * i + 1] = vb.y;
        }
    }

    // Epoch base (floor to multiple of ARR_PER_STEP; see g_ctr comment).
    const unsigned base = ld_acq(&g_ctr) & ~(ARR_PER_STEP - 1u);

    // Step 0: h_0 = 0  =>  Y[0] = tanh(pre[0]); per-warp arrival.
    if (lane == 0) {
        const float2 p0 = *(const float2*)(g_pre + row0);
        float2 o;
        o.x = tanhf(p0.x);
        o.y = tanhf(p0.y);
        *(float2*)(Y + row0) = o;
        red_rel_add1(&g_ctr);   // release orders this warp's stores
    }

    // Prefetch pre for step 1.
    float2 pv = *(const float2*)(g_pre + (size_t)N_DIM + row0);

    for (int t = 1; t < T_STEPS; t++) {
        // Wait until all 1024 warp-arrivals for step t-1 have landed.
        if (tid == 0) {
            const unsigned target = base + ARR_PER_STEP * (unsigned)t;
            while ((int)(ld_acq(&g_ctr) - target) < 0) {
                __nanosleep(64);
            }
        }
        __syncthreads();

        // Dot products: rows row0, row0+1 against h_{t-1} = Y[t-1].
        const ulonglong2* Yp = (const ulonglong2*)(Y + (size_t)(t - 1) * N_DIM);
        unsigned long long acc00 = 0ull, acc01 = 0ull, acc10 = 0ull, acc11 = 0ull;
#pragma unroll
        for (int i = 0; i < 16; i++) {
            ulonglong2 hv = Yp[i * 32 + lane];
            fma2(acc00, wA[2 * i],     hv.x);
            fma2(acc01, wA[2 * i + 1], hv.y);
            fma2(acc10, wB[2 * i],     hv.x);
            fma2(acc11, wB[2 * i + 1], hv.y);
        }
        float r0 = hsum2(add2(acc00, acc01));
        float r1 = hsum2(add2(acc10, acc11));

#pragma unroll
        for (int o = 16; o; o >>= 1) {
            r0 += __shfl_xor_sync(0xffffffffu, r0, o);
            r1 += __shfl_xor_sync(0xffffffffu, r1, o);
        }

        // Prefetch next step's pre while the result is written.
        float2 pnext = pv;
        if (t + 1 < T_STEPS)
            pnext = *(const float2*)(g_pre + (size_t)(t + 1) * N_DIM + row0);

        // Publish per-warp: lane0 wrote this warp's two h values itself, so
        // its release-arrival orders exactly the data consumers will read.
        if (lane == 0) {
            float2 o;
            o.x = tanhf(pv.x + r0);
            o.y = tanhf(pv.y + r1);
            *(float2*)(Y + (size_t)t * N_DIM + row0) = o;
            red_rel_add1(&g_ctr);
        }
        pv = pnext;
    }
}

// ---------------------------------------------------------------------------
extern "C" void kernel_launch(void* const* d_in, const int* in_sizes, int n_in,
                              void* d_out, int out_size)
{
    const float* X   = (const float*)d_in[0];   // [T, M]
    const float* Wih = (const float*)d_in[1];   // [N, M]
    const float* Whh = (const float*)d_in[2];   // [N, N]
    const float* bih = (const float*)d_in[3];   // [N]
    const float* bhh = (const float*)d_in[4];   // [N]
    float* Y = (float*)d_out;                   // [T, N]

    dim3 ggrid(T_STEPS / 128, N_DIM / 128);
    gemm_pre_kernel<<<ggrid, 256>>>(X, Wih, bih, bhh);

    rnn_kernel<<<GBLOCKS, RNN_THREADS>>>(Whh, Y);
}

// round 17
// speedup vs baseline: 1.2216x; 1.2216x over previous
#include <cuda_runtime.h>
#include <math.h>

#define T_STEPS 8192
#define M_DIM   1024
#define N_DIM   2048

#define GBLOCKS        128
#define ROWS_PER_BLOCK 16    // N_DIM / GBLOCKS
#define RNN_THREADS    256
#define NCTR           4     // split arrival counters
#define BLKS_PER_CTR   32u   // 128 / NCTR

// Scratch for the batched input projection (allocation-free rule: device global).
__device__ float g_pre[(size_t)T_STEPS * N_DIM];

// FOUR monotone arrival counters, 128B apart (separate L2 lines/sectors).
// Block b arrives at counter b&3 once per step (after its bottom barrier).
// Per launch each counter receives 32 * 8192 adds == 0 mod 32 and starts at
// 0, so at every launch boundary each counter is a multiple of 32. Before
// any block reads its bases, fewer than 32 foreign step-0 arrivals can exist
// per counter (a block reads bases before its own arrival; any step-1
// arrival requires ALL 128 step-0 arrivals, hence all base reads). So
// flooring each counter's first read to a multiple of 32 yields consistent
// per-counter epoch bases. Signed compares handle wrap; monotone, no resets
// -> graph-replay safe, deadlock-free.
__device__ unsigned g_ctrs[NCTR * 32];   // counter c at g_ctrs[c*32]

// ---------------------------------------------------------------------------
// Inline PTX helpers
// ---------------------------------------------------------------------------
__device__ __forceinline__ unsigned ld_acq(const unsigned* p) {
    unsigned v;
    asm volatile("ld.acquire.gpu.u32 %0, [%1];" : "=r"(v) : "l"(p) : "memory");
    return v;
}
__device__ __forceinline__ void red_rel_add1(unsigned* p) {
    asm volatile("red.release.gpu.global.add.u32 [%0], %1;"
                 :: "l"(p), "r"(1u) : "memory");
}
__device__ __forceinline__ void fma2(unsigned long long& d,
                                     unsigned long long a,
                                     unsigned long long b) {
    asm("fma.rn.f32x2 %0, %1, %2, %3;" : "=l"(d) : "l"(a), "l"(b), "l"(d));
}
__device__ __forceinline__ unsigned long long add2(unsigned long long a,
                                                   unsigned long long b) {
    unsigned long long d;
    asm("add.rn.f32x2 %0, %1, %2;" : "=l"(d) : "l"(a), "l"(b));
    return d;
}
__device__ __forceinline__ float hsum2(unsigned long long v) {
    float lo, hi;
    asm("mov.b64 {%0, %1}, %2;" : "=f"(lo), "=f"(hi) : "l"(v));
    return lo + hi;
}

// ---------------------------------------------------------------------------
// Kernel 1: pre = X @ W_ih^T + (b_ih + b_hh)   (unchanged, proven)
// ---------------------------------------------------------------------------
__global__ __launch_bounds__(256) void gemm_pre_kernel(
    const float* __restrict__ X,
    const float* __restrict__ Wih,
    const float* __restrict__ b_ih,
    const float* __restrict__ b_hh)
{
    __shared__ float As[8][128];
    __shared__ float Bs[8][128];

    const int tid = threadIdx.x;
    const int rowBase = blockIdx.x * 128;
    const int colBase = blockIdx.y * 128;
    const int tx = tid & 15;
    const int ty = tid >> 4;

    float acc[8][8];
#pragma unroll
    for (int i = 0; i < 8; i++)
#pragma unroll
        for (int j = 0; j < 8; j++) acc[i][j] = 0.0f;

    const int lr = tid >> 1;
    const int lq = (tid & 1) * 4;

    for (int k0 = 0; k0 < M_DIM; k0 += 8) {
        float4 av = *(const float4*)&X  [(size_t)(rowBase + lr) * M_DIM + k0 + lq];
        float4 bv = *(const float4*)&Wih[(size_t)(colBase + lr) * M_DIM + k0 + lq];

        __syncthreads();
        As[lq + 0][lr] = av.x;
        As[lq + 1][lr] = av.y;
        As[lq + 2][lr] = av.z;
        As[lq + 3][lr] = av.w;
        Bs[lq + 0][lr] = bv.x;
        Bs[lq + 1][lr] = bv.y;
        Bs[lq + 2][lr] = bv.z;
        Bs[lq + 3][lr] = bv.w;
        __syncthreads();

#pragma unroll
        for (int k = 0; k < 8; k++) {
            float4 a0 = ((const float4*)As[k])[ty];
            float4 a1 = ((const float4*)As[k])[ty + 16];
            float4 b0 = ((const float4*)Bs[k])[tx];
            float4 b1 = ((const float4*)Bs[k])[tx + 16];
            float a[8] = {a0.x, a0.y, a0.z, a0.w, a1.x, a1.y, a1.z, a1.w};
            float b[8] = {b0.x, b0.y, b0.z, b0.w, b1.x, b1.y, b1.z, b1.w};
#pragma unroll
            for (int i = 0; i < 8; i++)
#pragma unroll
                for (int j = 0; j < 8; j++)
                    acc[i][j] = fmaf(a[i], b[j], acc[i][j]);
        }
    }

    const int n0 = colBase + tx * 4;
    const int n1 = colBase + 64 + tx * 4;
    float bias[8];
#pragma unroll
    for (int j = 0; j < 4; j++) {
        bias[j]     = b_ih[n0 + j] + b_hh[n0 + j];
        bias[j + 4] = b_ih[n1 + j] + b_hh[n1 + j];
    }

#pragma unroll
    for (int i = 0; i < 8; i++) {
        int m = rowBase + ((i < 4) ? (ty * 4 + i) : (64 + ty * 4 + (i - 4)));
        float4 o0, o1;
        o0.x = acc[i][0] + bias[0];
        o0.y = acc[i][1] + bias[1];
        o0.z = acc[i][2] + bias[2];
        o0.w = acc[i][3] + bias[3];
        o1.x = acc[i][4] + bias[4];
        o1.y = acc[i][5] + bias[5];
        o1.z = acc[i][6] + bias[6];
        o1.w = acc[i][7] + bias[7];
        *(float4*)&g_pre[(size_t)m * N_DIM + n0] = o0;
        *(float4*)&g_pre[(size_t)m * N_DIM + n1] = o1;
    }
}

// ---------------------------------------------------------------------------
// Kernel 2: persistent RNN recurrence == the R12 17.06ms WINNER with exactly
// one change: the single arrival counter is split into 4 counters 128B apart.
//   arrive:  block-level (bottom __syncthreads + tid0 red.release.add to
//            counter b&3)  -> 32 adds/sector/step (was 128)
//   detect:  threads 0-3 each acquire-poll their own counter with
//            __nanosleep(128) -> 32 pollers/sector (was 128), well under the
//            LTS per-sector accept floor; __syncthreads composes the four
//            acquire edges block-wide (same cumulativity R12 relied on).
// Compute path byte-identical to R12.
// ---------------------------------------------------------------------------
__global__ __launch_bounds__(RNN_THREADS, 1) void rnn_kernel(
    const float* __restrict__ Whh,
    float* __restrict__ Y)
{
    const int tid  = threadIdx.x;
    const int b    = blockIdx.x;
    const int warp = tid >> 5;
    const int lane = tid & 31;
    const int row0 = b * ROWS_PER_BLOCK + 2 * warp;

    // Warp's two W_hh rows in registers, pre-packed as f32x2 pairs.
    unsigned long long wA[32], wB[32];
    {
        const ulonglong2* WA = (const ulonglong2*)(Whh + (size_t)row0 * N_DIM);
        const ulonglong2* WB = (const ulonglong2*)(Whh + (size_t)(row0 + 1) * N_DIM);
#pragma unroll
        for (int i = 0; i < 16; i++) {
            ulonglong2 va = WA[i * 32 + lane];
            ulonglong2 vb = WB[i * 32 + lane];
            wA[2 * i]     = va.x;
            wA[2 * i + 1] = va.y;
            wB[2 * i]     = vb.x;
            wB[2 * i + 1] = vb.y;
        }
    }

    // Per-counter epoch base for this block's poller thread (tid 0..3).
    // Floored to a multiple of 32 (see g_ctrs comment).
    unsigned my_base = 0;
    if (tid < NCTR)
        my_base = ld_acq(&g_ctrs[tid * 32]) & ~(BLKS_PER_CTR - 1u);

    // Step 0: h_0 = 0  =>  Y[0] = tanh(pre[0]).
    if (lane == 0) {
        const float2 p0 = *(const float2*)(g_pre + row0);
        float2 o;
        o.x = tanhf(p0.x);
        o.y = tanhf(p0.y);
        *(float2*)(Y + row0) = o;
    }
    __syncthreads();                    // all stores (and base reads) done
    if (tid == 0) red_rel_add1(&g_ctrs[(b & (NCTR - 1)) * 32]);

    // Prefetch pre for step 1.
    float2 pv = *(const float2*)(g_pre + (size_t)N_DIM + row0);

    for (int t = 1; t < T_STEPS; t++) {
        // Wait until all 128 blocks have published h_{t-1}: each poller
        // thread tracks its own counter (32 arrivals/step each).
        if (tid < NCTR) {
            const unsigned target = my_base + BLKS_PER_CTR * (unsigned)t;
            while ((int)(ld_acq(&g_ctrs[tid * 32]) - target) < 0) {
                __nanosleep(128);
            }
        }
        __syncthreads();

        // Dot products: rows row0, row0+1 against h_{t-1} = Y[t-1].
        const ulonglong2* Yp = (const ulonglong2*)(Y + (size_t)(t - 1) * N_DIM);
        unsigned long long acc00 = 0ull, acc01 = 0ull, acc10 = 0ull, acc11 = 0ull;
#pragma unroll
        for (int i = 0; i < 16; i++) {
            ulonglong2 hv = Yp[i * 32 + lane];
            fma2(acc00, wA[2 * i],     hv.x);
            fma2(acc01, wA[2 * i + 1], hv.y);
            fma2(acc10, wB[2 * i],     hv.x);
            fma2(acc11, wB[2 * i + 1], hv.y);
        }
        float r0 = hsum2(add2(acc00, acc01));
        float r1 = hsum2(add2(acc10, acc11));

#pragma unroll
        for (int o = 16; o; o >>= 1) {
            r0 += __shfl_xor_sync(0xffffffffu, r0, o);
            r1 += __shfl_xor_sync(0xffffffffu, r1, o);
        }

        // Prefetch next step's pre while the result is written.
        float2 pnext = pv;
        if (t + 1 < T_STEPS)
            pnext = *(const float2*)(g_pre + (size_t)(t + 1) * N_DIM + row0);

        if (lane == 0) {
            float2 o;
            o.x = tanhf(pv.x + r0);
            o.y = tanhf(pv.y + r1);
            *(float2*)(Y + (size_t)t * N_DIM + row0) = o;
        }
        pv = pnext;

        // Publish h_t: block barrier orders all warps' stores before the
        // release-arrival (R12-proven edge), to this block's counter.
        __syncthreads();
        if (tid == 0) red_rel_add1(&g_ctrs[(b & (NCTR - 1)) * 32]);
    }
}

// ---------------------------------------------------------------------------
extern "C" void kernel_launch(void* const* d_in, const int* in_sizes, int n_in,
                              void* d_out, int out_size)
{
    const float* X   = (const float*)d_in[0];   // [T, M]
    const float* Wih = (const float*)d_in[1];   // [N, M]
    const float* Whh = (const float*)d_in[2];   // [N, N]
    const float* bih = (const float*)d_in[3];   // [N]
    const float* bhh = (const float*)d_in[4];   // [N]
    float* Y = (float*)d_out;                   // [T, N]

    dim3 ggrid(T_STEPS / 128, N_DIM / 128);
    gemm_pre_kernel<<<ggrid, 256>>>(X, Wih, bih, bhh);

    rnn_kernel<<<GBLOCKS, RNN_THREADS>>>(Whh, Y);
}